// round 16
// baseline (speedup 1.0000x reference)
#include <cuda_runtime.h>
#include <cuda_bf16.h>
#include <math.h>

// ---------------- problem constants ----------------
#define NNODES   50000
#define NEDGES   800000
#define NH       256
#define EH       64
#define NSTEPS   10
#define EPSV     0.01f

// ---------------- scratch (device globals, no allocation) ----------------
__device__ float  g_hs[NNODES * 32];
__device__ float  g_hd[NNODES * 32];
__device__ int    g_deg[NNODES];
__device__ int    g_ptr[NNODES];
__device__ int    g_cursor[NNODES];
__device__ int    g_bsum[256];
__device__ int    g_boff[256];
__device__ float2 g_coef[NEDGES];
__device__ float4 g_ecsr[NEDGES];     // .x = elen, .y = 2*step, .z = src (bits)
__device__ float4 g_cA[NNODES];
__device__ float4 g_cB[NNODES];

// ============================================================
// tf32 mma + cp.async helpers
// ============================================================
__device__ __forceinline__ unsigned f2tf32(float f)
{
    unsigned u;
    asm("cvt.rna.tf32.f32 %0, %1;" : "=r"(u) : "f"(f));
    return u;
}

__device__ __forceinline__ void split_tf32(float v, unsigned& hi, unsigned& lo)
{
    hi = f2tf32(v);
    lo = f2tf32(v - __uint_as_float(hi));
}

__device__ __forceinline__ void mma_tf32(float4& d,
                                         unsigned a0, unsigned a1, unsigned a2, unsigned a3,
                                         unsigned b0, unsigned b1)
{
    asm volatile("mma.sync.aligned.m16n8k8.row.col.f32.tf32.tf32.f32 "
                 "{%0,%1,%2,%3}, {%4,%5,%6,%7}, {%8,%9}, {%0,%1,%2,%3};"
                 : "+f"(d.x), "+f"(d.y), "+f"(d.z), "+f"(d.w)
                 : "r"(a0), "r"(a1), "r"(a2), "r"(a3), "r"(b0), "r"(b1));
}

__device__ __forceinline__ void cp_async16(float* smem_ptr, const float* gptr)
{
    unsigned saddr = (unsigned)__cvta_generic_to_shared(smem_ptr);
    asm volatile("cp.async.cg.shared.global [%0], [%1], 16;" :: "r"(saddr), "l"(gptr));
}
#define CP_COMMIT() asm volatile("cp.async.commit_group;")
#define CP_WAIT0()  asm volatile("cp.async.wait_group 0;")

// ============================================================
// Kernel 1: node GEMM via tensor cores (3xTF32), cp.async pipelined
// C = node_emb @ [Wt1 | Ws | Wd]   (M x 256 x 192), TBK=16  [round-13 proven]
// ============================================================
#define TBM 64
#define TBN 192
#define TBK 16
#define ASTR 20
#define BSTR 200
#define NG_OFF_AL   1280
#define NG_OFF_BH   2560
#define NG_OFF_BL   5760
#define NG_OFF_RAWA 8960
#define NG_OFF_RAWB 9984
#define NG_OFF_RED  13056
#define NG_OFF_BT1  13248
#define NG_OFF_WT2  13376
#define NG_OFF_BT2  13760
#define NG_SMEM_BYTES ((13760 + 4) * 4)     // 55056 B

__global__ __launch_bounds__(256)
void node_gemm_tc(const float* __restrict__ A,      // node_emb [M,256]
                  const float* __restrict__ Wt1,    // [256,128]
                  const float* __restrict__ bt1,    // [128]
                  const float* __restrict__ Wt2,    // [128,3]
                  const float* __restrict__ bt2,    // [3]
                  const float* __restrict__ Wr1,    // [576,32]
                  float* __restrict__ out_torsion,
                  int M)
{
    extern __shared__ float smf[];
    unsigned* AsH  = reinterpret_cast<unsigned*>(smf);
    unsigned* AsL  = reinterpret_cast<unsigned*>(smf) + NG_OFF_AL;
    unsigned* BsH  = reinterpret_cast<unsigned*>(smf) + NG_OFF_BH;
    unsigned* BsL  = reinterpret_cast<unsigned*>(smf) + NG_OFF_BL;
    float* rawA    = smf + NG_OFF_RAWA;
    float* rawB    = smf + NG_OFF_RAWB;
    float* red     = smf + NG_OFF_RED;
    float* sbt1    = smf + NG_OFF_BT1;
    float* sWt2    = smf + NG_OFF_WT2;
    float* sbt2    = smf + NG_OFF_BT2;

    const int tid  = threadIdx.x;
    const int lane = tid & 31;
    const int warp = tid >> 5;
    const int gid  = lane >> 2;
    const int tg   = lane & 3;
    const int wm   = warp >> 2;
    const int wn   = warp & 3;
    const int m0   = blockIdx.x * TBM;

    if (tid < 128) {
        sbt1[tid] = bt1[tid];
        sWt2[tid * 3 + 0] = Wt2[tid * 3 + 0];
        sWt2[tid * 3 + 1] = Wt2[tid * 3 + 1];
        sWt2[tid * 3 + 2] = Wt2[tid * 3 + 2];
    }
    if (tid < 3) sbt2[tid] = bt2[tid];
    if (tid < 192) red[tid] = 0.f;

    const int a_row = tid >> 2, a_c4 = tid & 3;
    int a_m = m0 + a_row; if (a_m > M - 1) a_m = M - 1;
    const float* a_src = A + (size_t)a_m * NH + a_c4 * 4;
    float* a_dst = rawA + tid * 4;

    int   b_row[3], b_q[3];
#pragma unroll
    for (int i = 0; i < 3; i++) {
        int idx = tid + 256 * i;
        b_row[i] = idx / 48;
        b_q[i]   = idx - b_row[i] * 48;
    }

    auto issue_tile = [&](int kb) {
        cp_async16(a_dst, a_src + kb);
#pragma unroll
        for (int i = 0; i < 3; i++) {
            const float* src;
            int row = kb + b_row[i], q = b_q[i];
            if (q < 32)      src = Wt1 + (size_t)row * 128 + q * 4;
            else if (q < 40) src = Wr1 + (size_t)(64 + row) * 32 + (q - 32) * 4;
            else             src = Wr1 + (size_t)(320 + row) * 32 + (q - 40) * 4;
            cp_async16(rawB + (tid + 256 * i) * 4, src);
        }
        CP_COMMIT();
    };

    float4 acc[2][6];
#pragma unroll
    for (int i = 0; i < 2; i++)
#pragma unroll
        for (int j = 0; j < 6; j++) acc[i][j] = make_float4(0.f, 0.f, 0.f, 0.f);

    issue_tile(0);
    CP_WAIT0();

    for (int kb = 0; kb < NH; kb += TBK) {
        {
            float4 v = *reinterpret_cast<float4*>(a_dst);
            unsigned* dh = &AsH[a_row * ASTR + a_c4 * 4];
            unsigned* dl = &AsL[a_row * ASTR + a_c4 * 4];
            split_tf32(v.x, dh[0], dl[0]);
            split_tf32(v.y, dh[1], dl[1]);
            split_tf32(v.z, dh[2], dl[2]);
            split_tf32(v.w, dh[3], dl[3]);
        }
#pragma unroll
        for (int i = 0; i < 3; i++) {
            float4 v = *reinterpret_cast<float4*>(rawB + (tid + 256 * i) * 4);
            unsigned* dh = &BsH[b_row[i] * BSTR + b_q[i] * 4];
            unsigned* dl = &BsL[b_row[i] * BSTR + b_q[i] * 4];
            split_tf32(v.x, dh[0], dl[0]);
            split_tf32(v.y, dh[1], dl[1]);
            split_tf32(v.z, dh[2], dl[2]);
            split_tf32(v.w, dh[3], dl[3]);
        }
        __syncthreads();

        if (kb + TBK < NH) issue_tile(kb + TBK);

#pragma unroll
        for (int k8 = 0; k8 < 2; k8++) {
            const int kc = k8 * 8 + tg;
            unsigned aH[2][4], aL[2][4];
#pragma unroll
            for (int mf = 0; mf < 2; mf++) {
                int mr = wm * 32 + mf * 16 + gid;
                aH[mf][0] = AsH[mr * ASTR + kc];
                aH[mf][1] = AsH[(mr + 8) * ASTR + kc];
                aH[mf][2] = AsH[mr * ASTR + kc + 4];
                aH[mf][3] = AsH[(mr + 8) * ASTR + kc + 4];
                aL[mf][0] = AsL[mr * ASTR + kc];
                aL[mf][1] = AsL[(mr + 8) * ASTR + kc];
                aL[mf][2] = AsL[mr * ASTR + kc + 4];
                aL[mf][3] = AsL[(mr + 8) * ASTR + kc + 4];
            }
#pragma unroll
            for (int nf = 0; nf < 6; nf++) {
                int n = wn * 48 + nf * 8 + gid;
                unsigned bH0 = BsH[kc * BSTR + n];
                unsigned bH1 = BsH[(kc + 4) * BSTR + n];
                unsigned bL0 = BsL[kc * BSTR + n];
                unsigned bL1 = BsL[(kc + 4) * BSTR + n];
#pragma unroll
                for (int mf = 0; mf < 2; mf++) {
                    mma_tf32(acc[mf][nf], aH[mf][0], aH[mf][1], aH[mf][2], aH[mf][3], bL0, bL1);
                    mma_tf32(acc[mf][nf], aL[mf][0], aL[mf][1], aL[mf][2], aL[mf][3], bH0, bH1);
                    mma_tf32(acc[mf][nf], aH[mf][0], aH[mf][1], aH[mf][2], aH[mf][3], bH0, bH1);
                }
            }
        }
        CP_WAIT0();
        __syncthreads();
    }

    // ---- epilogue ----
    float p[2][2][3];
#pragma unroll
    for (int i = 0; i < 2; i++)
#pragma unroll
        for (int h = 0; h < 2; h++)
            p[i][h][0] = p[i][h][1] = p[i][h][2] = 0.f;

#pragma unroll
    for (int mf = 0; mf < 2; mf++) {
#pragma unroll
        for (int nf = 0; nf < 6; nf++) {
            int c = wn * 48 + nf * 8 + 2 * tg;
            int rl0 = wm * 32 + mf * 16 + gid;
            float4 d = acc[mf][nf];
            if (c >= 128) {
                float* base; int cc;
                if (c < 160) { base = g_hs; cc = c - 128; }
                else         { base = g_hd; cc = c - 160; }
                int mA = m0 + rl0, mB = mA + 8;
                if (mA < M) *reinterpret_cast<float2*>(base + (size_t)mA * 32 + cc) = make_float2(d.x, d.y);
                if (mB < M) *reinterpret_cast<float2*>(base + (size_t)mB * 32 + cc) = make_float2(d.z, d.w);
            } else {
                float b0 = sbt1[c], b1 = sbt1[c + 1];
                float w00 = sWt2[c * 3 + 0], w01 = sWt2[c * 3 + 1], w02 = sWt2[c * 3 + 2];
                float w10 = sWt2[(c + 1) * 3 + 0], w11 = sWt2[(c + 1) * 3 + 1], w12 = sWt2[(c + 1) * 3 + 2];
                float h0 = d.x + b0; h0 = (h0 >= 0.f) ? h0 : 0.01f * h0;
                float h1 = d.y + b1; h1 = (h1 >= 0.f) ? h1 : 0.01f * h1;
                p[mf][0][0] = fmaf(h0, w00, fmaf(h1, w10, p[mf][0][0]));
                p[mf][0][1] = fmaf(h0, w01, fmaf(h1, w11, p[mf][0][1]));
                p[mf][0][2] = fmaf(h0, w02, fmaf(h1, w12, p[mf][0][2]));
                float h2 = d.z + b0; h2 = (h2 >= 0.f) ? h2 : 0.01f * h2;
                float h3 = d.w + b1; h3 = (h3 >= 0.f) ? h3 : 0.01f * h3;
                p[mf][1][0] = fmaf(h2, w00, fmaf(h3, w10, p[mf][1][0]));
                p[mf][1][1] = fmaf(h2, w01, fmaf(h3, w11, p[mf][1][1]));
                p[mf][1][2] = fmaf(h2, w02, fmaf(h3, w12, p[mf][1][2]));
            }
        }
    }
#pragma unroll
    for (int mf = 0; mf < 2; mf++)
#pragma unroll
        for (int h = 0; h < 2; h++)
#pragma unroll
            for (int j = 0; j < 3; j++) {
                float v = p[mf][h][j];
                v += __shfl_xor_sync(0xffffffffu, v, 1);
                v += __shfl_xor_sync(0xffffffffu, v, 2);
                p[mf][h][j] = v;
            }
    if (tg == 0 && wn < 3) {
#pragma unroll
        for (int mf = 0; mf < 2; mf++)
#pragma unroll
            for (int h = 0; h < 2; h++) {
                int rl = wm * 32 + mf * 16 + gid + 8 * h;
                atomicAdd(&red[rl * 3 + 0], p[mf][h][0]);
                atomicAdd(&red[rl * 3 + 1], p[mf][h][1]);
                atomicAdd(&red[rl * 3 + 2], p[mf][h][2]);
            }
    }
    __syncthreads();

    if (tid < 64) {
        int m = m0 + tid;
        if (m < M) {
            float t0 = red[tid * 3 + 0] + sbt2[0];
            float t1 = red[tid * 3 + 1] + sbt2[1];
            float t2 = red[tid * 3 + 2] + sbt2[2];
            float rho = sqrtf(t0 * t0 + t1 * t1 + t2 * t2);
            float inv = 1.0f / rho;
            float n0 = t0 * inv, n1 = t1 * inv, n2 = t2 * inv;
            float theta = (fabsf(n0) > fabsf(n1)) ? atan2f(n1, n0)
                                                  : (1.5707963267948966f - atan2f(n0, n1));
            float cz = fminf(fmaxf(n2, -1.0f + EPSV), 1.0f - EPSV);
            float phi = acosf(cz);
            out_torsion[(size_t)m * 3 + 0] = rho;
            out_torsion[(size_t)m * 3 + 1] = phi;
            out_torsion[(size_t)m * 3 + 2] = theta;
        }
    }
}

// ============================================================
// CSR build
// ============================================================
__global__ void init_kernel(const float* __restrict__ cart, int N)
{
    int n = blockIdx.x * blockDim.x + threadIdx.x;
    if (n >= N) return;
    g_cA[n] = make_float4(cart[n * 3 + 0], cart[n * 3 + 1], cart[n * 3 + 2], 0.f);
    g_deg[n] = 0;
}

__global__ void count_kernel(const int* __restrict__ eidx, int E)
{
    int e = blockIdx.x * blockDim.x + threadIdx.x;
    if (e >= E) return;
    atomicAdd(&g_deg[eidx[E + e]], 1);
}

__global__ void scan1_kernel(int N)
{
    __shared__ int s[256];
    int t = threadIdx.x;
    int n = blockIdx.x * 256 + t;
    int v = (n < N) ? g_deg[n] : 0;
    s[t] = v;
    __syncthreads();
#pragma unroll
    for (int o = 1; o < 256; o <<= 1) {
        int x = (t >= o) ? s[t - o] : 0;
        __syncthreads();
        s[t] += x;
        __syncthreads();
    }
    if (n < N) g_ptr[n] = s[t] - v;
    if (t == 255) g_bsum[blockIdx.x] = s[255];
}

__global__ void scan2_kernel(int nb)
{
    __shared__ int s[256];
    int t = threadIdx.x;
    int v = (t < nb) ? g_bsum[t] : 0;
    s[t] = v;
    __syncthreads();
#pragma unroll
    for (int o = 1; o < 256; o <<= 1) {
        int x = (t >= o) ? s[t - o] : 0;
        __syncthreads();
        s[t] += x;
        __syncthreads();
    }
    if (t < nb) g_boff[t] = s[t] - v;
}

__global__ void scan3_kernel(int N)
{
    int n = blockIdx.x * blockDim.x + threadIdx.x;
    if (n >= N) return;
    int p = g_ptr[n] + g_boff[n >> 8];
    g_ptr[n] = p;
    g_cursor[n] = p;
}

// fill: merge per-edge coef + src into CSR slot (full 16B store)
__global__ void fill_kernel(const int* __restrict__ eidx, int E)
{
    int e = blockIdx.x * blockDim.x + threadIdx.x;
    if (e >= E) return;
    int s = eidx[e];
    int d = eidx[E + e];
    float2 cf = g_coef[e];
    int slot = atomicAdd(&g_cursor[d], 1);
    g_ecsr[slot] = make_float4(cf.x, cf.y, __int_as_float(s), 0.f);
}

// ============================================================
// Kernel 2: edge MLP via tensor cores (3xTF32), fused epilogue
// 64 edges/block, 256 threads (8 warps, 4m x 2n), warp tile m16 x n16
// smem 55.7 KB -> 4 blocks/SM (occ 2x vs 128-edge version)
// ============================================================
#define EA_STR 68
#define EB_STR 40
#define EOFF_AL 4352            // 64*68
#define EOFF_BH 8704
#define EOFF_BL 11264           // +64*40
#define EOFF_W2 13824
#define EOFF_SB 13888
#define ESMEM_BYTES ((13888 + 40) * 4)   // 55712 B

__global__ __launch_bounds__(256)
void edge_mlp_tc(const float* __restrict__ edge_emb,  // [E,64]
                 const float* __restrict__ Wr1,       // [576,32]
                 const float* __restrict__ br1,       // [32]
                 const float* __restrict__ Wr2,       // [32,2]
                 const float* __restrict__ br2,       // [2]
                 const int*   __restrict__ eidx,      // [2,E]
                 int E)
{
    extern __shared__ unsigned sm_u[];
    unsigned* AsH = sm_u;
    unsigned* AsL = sm_u + EOFF_AL;
    unsigned* BsH = sm_u + EOFF_BH;
    unsigned* BsL = sm_u + EOFF_BL;
    float* sWr2   = reinterpret_cast<float*>(sm_u + EOFF_W2);
    float* sb     = reinterpret_cast<float*>(sm_u + EOFF_SB);
    float* Hs     = reinterpret_cast<float*>(sm_u);   // [64][36], reused after mainloop

    const int tid  = threadIdx.x;
    const int lane = tid & 31;
    const int warp = tid >> 5;
    const int gid  = lane >> 2;
    const int tg   = lane & 3;
    const int wm   = warp >> 1;     // 0..3
    const int wn   = warp & 1;      // 0..1
    const int eb   = blockIdx.x * 64;

    if (tid < 64) sWr2[tid] = Wr2[tid];
    if (tid < 32) sb[tid] = br1[tid];
    if (tid < 2)  sb[32 + tid] = br2[tid];

    // stage We (64x32): 512 float4, 2 per thread, hi/lo split
#pragma unroll
    for (int j = 0; j < 2; j++) {
        int idx = tid + 256 * j;
        int k = idx >> 3, c4 = idx & 7;
        float4 v = *reinterpret_cast<const float4*>(Wr1 + k * 32 + c4 * 4);
        unsigned* dh = &BsH[k * EB_STR + c4 * 4];
        unsigned* dl = &BsL[k * EB_STR + c4 * 4];
        split_tf32(v.x, dh[0], dl[0]);
        split_tf32(v.y, dh[1], dl[1]);
        split_tf32(v.z, dh[2], dl[2]);
        split_tf32(v.w, dh[3], dl[3]);
    }
    // stage A (64 edge rows x 64): 1024 float4, 4 per thread, hi/lo split
#pragma unroll
    for (int j = 0; j < 4; j++) {
        int idx = tid + 256 * j;
        int e = idx >> 4, q = idx & 15;
        float4 v = *reinterpret_cast<const float4*>(edge_emb + (size_t)(eb + e) * 64 + q * 4);
        unsigned* dh = &AsH[e * EA_STR + q * 4];
        unsigned* dl = &AsL[e * EA_STR + q * 4];
        split_tf32(v.x, dh[0], dl[0]);
        split_tf32(v.y, dh[1], dl[1]);
        split_tf32(v.z, dh[2], dl[2]);
        split_tf32(v.w, dh[3], dl[3]);
    }
    __syncthreads();

    // mainloop: warp tile rows wm*16..+15, cols wn*16..+15, K=64
    float4 acc[2];
    acc[0] = make_float4(0.f, 0.f, 0.f, 0.f);
    acc[1] = make_float4(0.f, 0.f, 0.f, 0.f);

    const int row0 = wm * 16 + gid;
#pragma unroll
    for (int k8 = 0; k8 < 8; k8++) {
        const int kc = k8 * 8 + tg;
        unsigned aH0 = AsH[row0 * EA_STR + kc];
        unsigned aH1 = AsH[(row0 + 8) * EA_STR + kc];
        unsigned aH2 = AsH[row0 * EA_STR + kc + 4];
        unsigned aH3 = AsH[(row0 + 8) * EA_STR + kc + 4];
        unsigned aL0 = AsL[row0 * EA_STR + kc];
        unsigned aL1 = AsL[(row0 + 8) * EA_STR + kc];
        unsigned aL2 = AsL[row0 * EA_STR + kc + 4];
        unsigned aL3 = AsL[(row0 + 8) * EA_STR + kc + 4];
#pragma unroll
        for (int nf = 0; nf < 2; nf++) {
            int n = wn * 16 + nf * 8 + gid;
            unsigned bH0 = BsH[kc * EB_STR + n];
            unsigned bH1 = BsH[(kc + 4) * EB_STR + n];
            unsigned bL0 = BsL[kc * EB_STR + n];
            unsigned bL1 = BsL[(kc + 4) * EB_STR + n];
            mma_tf32(acc[nf], aH0, aH1, aH2, aH3, bL0, bL1);
            mma_tf32(acc[nf], aL0, aL1, aL2, aL3, bH0, bH1);
            mma_tf32(acc[nf], aH0, aH1, aH2, aH3, bH0, bH1);
        }
    }
    __syncthreads();     // everyone done reading As/Bs before Hs overlay

    // acc -> Hs[64][36]
#pragma unroll
    for (int nf = 0; nf < 2; nf++) {
        int n0 = wn * 16 + nf * 8 + 2 * tg;
        *reinterpret_cast<float2*>(&Hs[row0 * 36 + n0])       = make_float2(acc[nf].x, acc[nf].y);
        *reinterpret_cast<float2*>(&Hs[(row0 + 8) * 36 + n0]) = make_float2(acc[nf].z, acc[nf].w);
    }
    __syncthreads();

    // epilogue: thread quad per edge (one edge per quad)
    const int eg = tid >> 2;     // 0..63
    const int dg = tid & 3;      // 0..3
    {
        int ge = eb + eg;
        int s = eidx[ge];
        int d = eidx[E + ge];
        float4 a0  = *reinterpret_cast<const float4*>(&Hs[eg * 36 + dg * 8]);
        float4 a1  = *reinterpret_cast<const float4*>(&Hs[eg * 36 + dg * 8 + 4]);
        float4 hs0 = *reinterpret_cast<const float4*>(g_hs + s * 32 + dg * 8);
        float4 hs1 = *reinterpret_cast<const float4*>(g_hs + s * 32 + dg * 8 + 4);
        float4 hd0 = *reinterpret_cast<const float4*>(g_hd + d * 32 + dg * 8);
        float4 hd1 = *reinterpret_cast<const float4*>(g_hd + d * 32 + dg * 8 + 4);
        float av[8]  = {a0.x, a0.y, a0.z, a0.w, a1.x, a1.y, a1.z, a1.w};
        float add[8] = {hs0.x + hd0.x, hs0.y + hd0.y, hs0.z + hd0.z, hs0.w + hd0.w,
                        hs1.x + hd1.x, hs1.y + hd1.y, hs1.z + hd1.z, hs1.w + hd1.w};
        float v0 = 0.f, v1 = 0.f;
#pragma unroll
        for (int j = 0; j < 8; j++) {
            float h = av[j] + add[j] + sb[dg * 8 + j];
            h = (h >= 0.f) ? h : 0.01f * h;
            v0 = fmaf(h, sWr2[(dg * 8 + j) * 2 + 0], v0);
            v1 = fmaf(h, sWr2[(dg * 8 + j) * 2 + 1], v1);
        }
        v0 += __shfl_xor_sync(0xffffffffu, v0, 1);
        v0 += __shfl_xor_sync(0xffffffffu, v0, 2);
        v1 += __shfl_xor_sync(0xffffffffu, v1, 1);
        v1 += __shfl_xor_sync(0xffffffffu, v1, 2);
        if (dg == 0) {
            float x = v0 + sb[32] + 1.0f;
            float elen = fmaxf(x, 0.f) + log1pf(expf(-fabsf(x)));
            float y = v1 + sb[33] - 2.0f;
            float sg = 1.0f / (1.0f + expf(-y));
            g_coef[ge] = make_float2(elen, 2.0f * sg);
        }
    }
}

// ============================================================
// Refiner: quad-per-node gather (round-13 proven)
// ============================================================
__global__ __launch_bounds__(256)
void refine_step_kernel(const float4* __restrict__ cin, float4* __restrict__ cout,
                        float* __restrict__ out_coords, int last, int N)
{
    const int tid = threadIdx.x;
    const int q   = tid & 3;
    const int nl  = tid >> 2;
    const int n   = blockIdx.x * 64 + nl;
    if (n >= N) return;

    float4 c = cin[n];
    const int p = g_ptr[n];
    const int d = g_deg[n];

    float ax = 0.f, ay = 0.f, az = 0.f;
    for (int i = q; i < d; i += 4) {
        float4 er = g_ecsr[p + i];
        int s = __float_as_int(er.z);
        float4 cs = __ldg(cin + s);
        float dx = c.x - cs.x, dy = c.y - cs.y, dz = c.z - cs.z;
        float dist = sqrtf(dx * dx + dy * dy + dz * dz);
        float f = __fdividef(er.y * (er.x - dist), dist + EPSV);
        ax = fmaf(f, dx, ax);
        ay = fmaf(f, dy, ay);
        az = fmaf(f, dz, az);
    }
    ax += __shfl_xor_sync(0xffffffffu, ax, 1);
    ax += __shfl_xor_sync(0xffffffffu, ax, 2);
    ay += __shfl_xor_sync(0xffffffffu, ay, 1);
    ay += __shfl_xor_sync(0xffffffffu, ay, 2);
    az += __shfl_xor_sync(0xffffffffu, az, 1);
    az += __shfl_xor_sync(0xffffffffu, az, 2);

    if (q == 0) {
        float an = sqrtf(ax * ax + ay * ay + az * az) + EPSV;
        float sc = fminf(an, 0.5f) / an;
        c.x += ax * sc; c.y += ay * sc; c.z += az * sc;
        cout[n] = c;
        if (last) {
            out_coords[n * 3 + 0] = c.x;
            out_coords[n * 3 + 1] = c.y;
            out_coords[n * 3 + 2] = c.z;
        }
    }
}

// ============================================================
// launch — two-stream fork/join (graph-capturable)
// ============================================================
extern "C" void kernel_launch(void* const* d_in, const int* in_sizes, int n_in,
                              void* d_out, int out_size)
{
    const float* node_emb  = (const float*)d_in[0];
    const float* edge_emb  = (const float*)d_in[1];
    const float* cart_init = (const float*)d_in[2];
    const float* Wt1       = (const float*)d_in[3];
    const float* bt1       = (const float*)d_in[4];
    const float* Wt2       = (const float*)d_in[5];
    const float* bt2       = (const float*)d_in[6];
    const float* Wr1       = (const float*)d_in[7];
    const float* br1       = (const float*)d_in[8];
    const float* Wr2       = (const float*)d_in[9];
    const float* br2       = (const float*)d_in[10];
    const int*   eidx      = (const int*)d_in[11];

    const int M = in_sizes[0] / NH;        // 50000
    const int E = in_sizes[1] / EH;        // 800000

    float* out = (float*)d_out;
    float* out_coords  = out;
    float* out_torsion = out + (size_t)M * 3;

    static cudaStream_t s2 = nullptr;
    static cudaEvent_t evFork = nullptr, evJoin = nullptr;
    if (!s2) {
        cudaStreamCreateWithFlags(&s2, cudaStreamNonBlocking);
        cudaEventCreateWithFlags(&evFork, cudaEventDisableTiming);
        cudaEventCreateWithFlags(&evJoin, cudaEventDisableTiming);
        cudaFuncSetAttribute(edge_mlp_tc, cudaFuncAttributeMaxDynamicSharedMemorySize,
                             ESMEM_BYTES);
        cudaFuncSetAttribute(node_gemm_tc, cudaFuncAttributeMaxDynamicSharedMemorySize,
                             NG_SMEM_BYTES);
    }

    const int nb_nodes = (M + 255) / 256;
    const int nb_edges = (E + 255) / 256;
    const int nb_emlp  = (E + 63) / 64;
    const int nb_ref   = (M + 63) / 64;

    // fork: CSR-build chain on side stream s2
    cudaEventRecord(evFork, 0);
    cudaStreamWaitEvent(s2, evFork, 0);

    // --- call order: capture index 3 = edge_mlp_tc (profiled) ---
    init_kernel<<<nb_nodes, 256, 0, s2>>>(cart_init, M);                         // 0
    count_kernel<<<nb_edges, 256, 0, s2>>>(eidx, E);                             // 1
    node_gemm_tc<<<(M + TBM - 1) / TBM, 256, NG_SMEM_BYTES>>>(node_emb, Wt1,     // 2
                                               bt1, Wt2, bt2, Wr1,
                                               out_torsion, M);
    edge_mlp_tc<<<nb_emlp, 256, ESMEM_BYTES>>>(edge_emb, Wr1, br1, Wr2, br2,     // 3
                                               eidx, E);
    scan1_kernel<<<nb_nodes, 256, 0, s2>>>(M);                                   // 4
    scan2_kernel<<<1, 256, 0, s2>>>(nb_nodes);                                   // 5
    scan3_kernel<<<nb_nodes, 256, 0, s2>>>(M);                                   // 6

    // join: fill needs cursor (s2) + coef (stream 0)
    cudaEventRecord(evJoin, s2);
    cudaStreamWaitEvent(0, evJoin, 0);

    fill_kernel<<<nb_edges, 256>>>(eidx, E);                                     // 7

    float4* bufs[2];
    cudaGetSymbolAddress((void**)&bufs[0], g_cA);
    cudaGetSymbolAddress((void**)&bufs[1], g_cB);
    for (int s = 0; s < NSTEPS; s++) {
        refine_step_kernel<<<nb_ref, 256>>>(bufs[s & 1], bufs[(s + 1) & 1],
                                            out_coords, (s == NSTEPS - 1) ? 1 : 0, M);
    }
}

// round 17
// speedup vs baseline: 1.0391x; 1.0391x over previous
#include <cuda_runtime.h>
#include <cuda_bf16.h>
#include <math.h>

// ---------------- problem constants ----------------
#define NNODES   50000
#define NEDGES   800000
#define NH       256
#define EH       64
#define NSTEPS   10
#define EPSV     0.01f

// ---------------- scratch (device globals, no allocation) ----------------
__device__ float  g_hs[NNODES * 32];
__device__ float  g_hd[NNODES * 32];
__device__ int    g_deg[NNODES];
__device__ int    g_ptr[NNODES];
__device__ int    g_cursor[NNODES];
__device__ int    g_bsum[256];
__device__ int    g_boff[256];
__device__ float2 g_coef[NEDGES];
__device__ float4 g_ecsr[NEDGES];     // .x = elen, .y = 2*step, .z = src (bits)
__device__ float4 g_cA[NNODES];
__device__ float4 g_cB[NNODES];
// pre-split weights (hi/lo tf32)
__device__ float  g_nBH[256 * 192];   // concat [Wt1 | Ws | Wd] hi
__device__ float  g_nBL[256 * 192];   // lo
__device__ float  g_eWH[64 * 32];     // We hi
__device__ float  g_eWL[64 * 32];     // We lo

// ============================================================
// tf32 mma + cp.async helpers
// ============================================================
__device__ __forceinline__ unsigned f2tf32(float f)
{
    unsigned u;
    asm("cvt.rna.tf32.f32 %0, %1;" : "=r"(u) : "f"(f));
    return u;
}

__device__ __forceinline__ void split_tf32(float v, unsigned& hi, unsigned& lo)
{
    hi = f2tf32(v);
    lo = f2tf32(v - __uint_as_float(hi));
}

__device__ __forceinline__ void mma_tf32(float4& d,
                                         unsigned a0, unsigned a1, unsigned a2, unsigned a3,
                                         unsigned b0, unsigned b1)
{
    asm volatile("mma.sync.aligned.m16n8k8.row.col.f32.tf32.tf32.f32 "
                 "{%0,%1,%2,%3}, {%4,%5,%6,%7}, {%8,%9}, {%0,%1,%2,%3};"
                 : "+f"(d.x), "+f"(d.y), "+f"(d.z), "+f"(d.w)
                 : "r"(a0), "r"(a1), "r"(a2), "r"(a3), "r"(b0), "r"(b1));
}

__device__ __forceinline__ void cp_async16(const void* smem_ptr, const void* gptr)
{
    unsigned saddr = (unsigned)__cvta_generic_to_shared(smem_ptr);
    asm volatile("cp.async.cg.shared.global [%0], [%1], 16;" :: "r"(saddr), "l"(gptr));
}
#define CP_COMMIT() asm volatile("cp.async.commit_group;")
#define CP_WAIT0()  asm volatile("cp.async.wait_group 0;")

// ============================================================
// Kernel 0: one-shot weight pre-split (hi/lo tf32)
// ============================================================
__global__ void presplit_kernel(const float* __restrict__ Wt1,   // [256,128]
                                const float* __restrict__ Wr1)   // [576,32]
{
    int idx = blockIdx.x * blockDim.x + threadIdx.x;
    if (idx < 256 * 192) {
        int k = idx / 192, n = idx - k * 192;
        float v;
        if (n < 128)      v = Wt1[k * 128 + n];
        else if (n < 160) v = Wr1[(64 + k) * 32 + (n - 128)];
        else              v = Wr1[(320 + k) * 32 + (n - 160)];
        unsigned h, l;
        split_tf32(v, h, l);
        g_nBH[idx] = __uint_as_float(h);
        g_nBL[idx] = __uint_as_float(l);
    } else if (idx < 256 * 192 + 64 * 32) {
        int i = idx - 256 * 192;
        unsigned h, l;
        split_tf32(Wr1[i], h, l);           // We = Wr1[0:64] row-major
        g_eWH[i] = __uint_as_float(h);
        g_eWL[i] = __uint_as_float(l);
    }
}

// ============================================================
// Kernel 1: node GEMM via tensor cores (3xTF32), cp.async pipelined
// B tiles: direct cp.async of pre-split weights into double-buffered Bs
// ============================================================
#define TBM 64
#define TBN 192
#define TBK 16
#define ASTR 20
#define BSTR 200
#define NG_OFF_AL   1280
#define NG_OFF_BH   2560            // 2 stages x 3200
#define NG_OFF_BL   8960            // 2 stages x 3200
#define NG_OFF_RAWA 15360
#define NG_OFF_RED  16384
#define NG_OFF_BT1  16576
#define NG_OFF_WT2  16704
#define NG_OFF_BT2  17088
#define NG_SMEM_BYTES ((17088 + 4) * 4)     // 68368 B

__global__ __launch_bounds__(256)
void node_gemm_tc(const float* __restrict__ A,      // node_emb [M,256]
                  const float* __restrict__ bt1,    // [128]
                  const float* __restrict__ Wt2,    // [128,3]
                  const float* __restrict__ bt2,    // [3]
                  float* __restrict__ out_torsion,
                  int M)
{
    extern __shared__ float smf[];
    unsigned* AsH  = reinterpret_cast<unsigned*>(smf);
    unsigned* AsL  = reinterpret_cast<unsigned*>(smf) + NG_OFF_AL;
    unsigned* BsH0 = reinterpret_cast<unsigned*>(smf) + NG_OFF_BH;
    unsigned* BsL0 = reinterpret_cast<unsigned*>(smf) + NG_OFF_BL;
    float* rawA    = smf + NG_OFF_RAWA;
    float* red     = smf + NG_OFF_RED;
    float* sbt1    = smf + NG_OFF_BT1;
    float* sWt2    = smf + NG_OFF_WT2;
    float* sbt2    = smf + NG_OFF_BT2;

    const int tid  = threadIdx.x;
    const int lane = tid & 31;
    const int warp = tid >> 5;
    const int gid  = lane >> 2;
    const int tg   = lane & 3;
    const int wm   = warp >> 2;
    const int wn   = warp & 3;
    const int m0   = blockIdx.x * TBM;

    if (tid < 128) {
        sbt1[tid] = bt1[tid];
        sWt2[tid * 3 + 0] = Wt2[tid * 3 + 0];
        sWt2[tid * 3 + 1] = Wt2[tid * 3 + 1];
        sWt2[tid * 3 + 2] = Wt2[tid * 3 + 2];
    }
    if (tid < 3) sbt2[tid] = bt2[tid];
    if (tid < 192) red[tid] = 0.f;

    const int a_row = tid >> 2, a_c4 = tid & 3;
    int a_m = m0 + a_row; if (a_m > M - 1) a_m = M - 1;
    const float* a_src = A + (size_t)a_m * NH + a_c4 * 4;
    float* a_dst = rawA + tid * 4;

    int   b_row[3], b_q[3];
#pragma unroll
    for (int i = 0; i < 3; i++) {
        int idx = tid + 256 * i;
        b_row[i] = idx / 48;
        b_q[i]   = idx - b_row[i] * 48;
    }

    // prefetch: A raw + B split (hi/lo) into stage st
    auto issue_tile = [&](int kb, int st) {
        cp_async16(a_dst, a_src + kb);
        unsigned* BH = BsH0 + st * 3200;
        unsigned* BL = BsL0 + st * 3200;
#pragma unroll
        for (int i = 0; i < 3; i++) {
            size_t goff = (size_t)(kb + b_row[i]) * 192 + b_q[i] * 4;
            cp_async16(&BH[b_row[i] * BSTR + b_q[i] * 4], g_nBH + goff);
            cp_async16(&BL[b_row[i] * BSTR + b_q[i] * 4], g_nBL + goff);
        }
        CP_COMMIT();
    };

    float4 acc[2][6];
#pragma unroll
    for (int i = 0; i < 2; i++)
#pragma unroll
        for (int j = 0; j < 6; j++) acc[i][j] = make_float4(0.f, 0.f, 0.f, 0.f);

    issue_tile(0, 0);
    CP_WAIT0();

    for (int kb = 0; kb < NH; kb += TBK) {
        const int st = (kb >> 4) & 1;
        // ---- convert A raw -> split smem ----
        {
            float4 v = *reinterpret_cast<float4*>(a_dst);
            unsigned* dh = &AsH[a_row * ASTR + a_c4 * 4];
            unsigned* dl = &AsL[a_row * ASTR + a_c4 * 4];
            split_tf32(v.x, dh[0], dl[0]);
            split_tf32(v.y, dh[1], dl[1]);
            split_tf32(v.z, dh[2], dl[2]);
            split_tf32(v.w, dh[3], dl[3]);
        }
        __syncthreads();

        // ---- prefetch next tile (A raw + B stage st^1), overlaps MMA ----
        if (kb + TBK < NH) issue_tile(kb + TBK, st ^ 1);

        const unsigned* BH = BsH0 + st * 3200;
        const unsigned* BL = BsL0 + st * 3200;
        // ---- MMA ----
#pragma unroll
        for (int k8 = 0; k8 < 2; k8++) {
            const int kc = k8 * 8 + tg;
            unsigned aH[2][4], aL[2][4];
#pragma unroll
            for (int mf = 0; mf < 2; mf++) {
                int mr = wm * 32 + mf * 16 + gid;
                aH[mf][0] = AsH[mr * ASTR + kc];
                aH[mf][1] = AsH[(mr + 8) * ASTR + kc];
                aH[mf][2] = AsH[mr * ASTR + kc + 4];
                aH[mf][3] = AsH[(mr + 8) * ASTR + kc + 4];
                aL[mf][0] = AsL[mr * ASTR + kc];
                aL[mf][1] = AsL[(mr + 8) * ASTR + kc];
                aL[mf][2] = AsL[mr * ASTR + kc + 4];
                aL[mf][3] = AsL[(mr + 8) * ASTR + kc + 4];
            }
#pragma unroll
            for (int nf = 0; nf < 6; nf++) {
                int n = wn * 48 + nf * 8 + gid;
                unsigned bH0 = BH[kc * BSTR + n];
                unsigned bH1 = BH[(kc + 4) * BSTR + n];
                unsigned bL0 = BL[kc * BSTR + n];
                unsigned bL1 = BL[(kc + 4) * BSTR + n];
#pragma unroll
                for (int mf = 0; mf < 2; mf++) {
                    mma_tf32(acc[mf][nf], aH[mf][0], aH[mf][1], aH[mf][2], aH[mf][3], bL0, bL1);
                    mma_tf32(acc[mf][nf], aL[mf][0], aL[mf][1], aL[mf][2], aL[mf][3], bH0, bH1);
                    mma_tf32(acc[mf][nf], aH[mf][0], aH[mf][1], aH[mf][2], aH[mf][3], bH0, bH1);
                }
            }
        }
        CP_WAIT0();
        __syncthreads();
    }

    // ---- epilogue ----
    float p[2][2][3];
#pragma unroll
    for (int i = 0; i < 2; i++)
#pragma unroll
        for (int h = 0; h < 2; h++)
            p[i][h][0] = p[i][h][1] = p[i][h][2] = 0.f;

#pragma unroll
    for (int mf = 0; mf < 2; mf++) {
#pragma unroll
        for (int nf = 0; nf < 6; nf++) {
            int c = wn * 48 + nf * 8 + 2 * tg;
            int rl0 = wm * 32 + mf * 16 + gid;
            float4 d = acc[mf][nf];
            if (c >= 128) {
                float* base; int cc;
                if (c < 160) { base = g_hs; cc = c - 128; }
                else         { base = g_hd; cc = c - 160; }
                int mA = m0 + rl0, mB = mA + 8;
                if (mA < M) *reinterpret_cast<float2*>(base + (size_t)mA * 32 + cc) = make_float2(d.x, d.y);
                if (mB < M) *reinterpret_cast<float2*>(base + (size_t)mB * 32 + cc) = make_float2(d.z, d.w);
            } else {
                float b0 = sbt1[c], b1 = sbt1[c + 1];
                float w00 = sWt2[c * 3 + 0], w01 = sWt2[c * 3 + 1], w02 = sWt2[c * 3 + 2];
                float w10 = sWt2[(c + 1) * 3 + 0], w11 = sWt2[(c + 1) * 3 + 1], w12 = sWt2[(c + 1) * 3 + 2];
                float h0 = d.x + b0; h0 = (h0 >= 0.f) ? h0 : 0.01f * h0;
                float h1 = d.y + b1; h1 = (h1 >= 0.f) ? h1 : 0.01f * h1;
                p[mf][0][0] = fmaf(h0, w00, fmaf(h1, w10, p[mf][0][0]));
                p[mf][0][1] = fmaf(h0, w01, fmaf(h1, w11, p[mf][0][1]));
                p[mf][0][2] = fmaf(h0, w02, fmaf(h1, w12, p[mf][0][2]));
                float h2 = d.z + b0; h2 = (h2 >= 0.f) ? h2 : 0.01f * h2;
                float h3 = d.w + b1; h3 = (h3 >= 0.f) ? h3 : 0.01f * h3;
                p[mf][1][0] = fmaf(h2, w00, fmaf(h3, w10, p[mf][1][0]));
                p[mf][1][1] = fmaf(h2, w01, fmaf(h3, w11, p[mf][1][1]));
                p[mf][1][2] = fmaf(h2, w02, fmaf(h3, w12, p[mf][1][2]));
            }
        }
    }
#pragma unroll
    for (int mf = 0; mf < 2; mf++)
#pragma unroll
        for (int h = 0; h < 2; h++)
#pragma unroll
            for (int j = 0; j < 3; j++) {
                float v = p[mf][h][j];
                v += __shfl_xor_sync(0xffffffffu, v, 1);
                v += __shfl_xor_sync(0xffffffffu, v, 2);
                p[mf][h][j] = v;
            }
    if (tg == 0 && wn < 3) {
#pragma unroll
        for (int mf = 0; mf < 2; mf++)
#pragma unroll
            for (int h = 0; h < 2; h++) {
                int rl = wm * 32 + mf * 16 + gid + 8 * h;
                atomicAdd(&red[rl * 3 + 0], p[mf][h][0]);
                atomicAdd(&red[rl * 3 + 1], p[mf][h][1]);
                atomicAdd(&red[rl * 3 + 2], p[mf][h][2]);
            }
    }
    __syncthreads();

    if (tid < 64) {
        int m = m0 + tid;
        if (m < M) {
            float t0 = red[tid * 3 + 0] + sbt2[0];
            float t1 = red[tid * 3 + 1] + sbt2[1];
            float t2 = red[tid * 3 + 2] + sbt2[2];
            float rho = sqrtf(t0 * t0 + t1 * t1 + t2 * t2);
            float inv = 1.0f / rho;
            float n0 = t0 * inv, n1 = t1 * inv, n2 = t2 * inv;
            float theta = (fabsf(n0) > fabsf(n1)) ? atan2f(n1, n0)
                                                  : (1.5707963267948966f - atan2f(n0, n1));
            float cz = fminf(fmaxf(n2, -1.0f + EPSV), 1.0f - EPSV);
            float phi = acosf(cz);
            out_torsion[(size_t)m * 3 + 0] = rho;
            out_torsion[(size_t)m * 3 + 1] = phi;
            out_torsion[(size_t)m * 3 + 2] = theta;
        }
    }
}

// ============================================================
// CSR build
// ============================================================
__global__ void init_kernel(const float* __restrict__ cart, int N)
{
    int n = blockIdx.x * blockDim.x + threadIdx.x;
    if (n >= N) return;
    g_cA[n] = make_float4(cart[n * 3 + 0], cart[n * 3 + 1], cart[n * 3 + 2], 0.f);
    g_deg[n] = 0;
}

__global__ void count_kernel(const int* __restrict__ eidx, int E)
{
    int e = blockIdx.x * blockDim.x + threadIdx.x;
    if (e >= E) return;
    atomicAdd(&g_deg[eidx[E + e]], 1);
}

__global__ void scan1_kernel(int N)
{
    __shared__ int s[256];
    int t = threadIdx.x;
    int n = blockIdx.x * 256 + t;
    int v = (n < N) ? g_deg[n] : 0;
    s[t] = v;
    __syncthreads();
#pragma unroll
    for (int o = 1; o < 256; o <<= 1) {
        int x = (t >= o) ? s[t - o] : 0;
        __syncthreads();
        s[t] += x;
        __syncthreads();
    }
    if (n < N) g_ptr[n] = s[t] - v;
    if (t == 255) g_bsum[blockIdx.x] = s[255];
}

__global__ void scan2_kernel(int nb)
{
    __shared__ int s[256];
    int t = threadIdx.x;
    int v = (t < nb) ? g_bsum[t] : 0;
    s[t] = v;
    __syncthreads();
#pragma unroll
    for (int o = 1; o < 256; o <<= 1) {
        int x = (t >= o) ? s[t - o] : 0;
        __syncthreads();
        s[t] += x;
        __syncthreads();
    }
    if (t < nb) g_boff[t] = s[t] - v;
}

__global__ void scan3_kernel(int N)
{
    int n = blockIdx.x * blockDim.x + threadIdx.x;
    if (n >= N) return;
    int p = g_ptr[n] + g_boff[n >> 8];
    g_ptr[n] = p;
    g_cursor[n] = p;
}

// fill: merge per-edge coef + src into CSR slot (full 16B store)
__global__ void fill_kernel(const int* __restrict__ eidx, int E)
{
    int e = blockIdx.x * blockDim.x + threadIdx.x;
    if (e >= E) return;
    int s = eidx[e];
    int d = eidx[E + e];
    float2 cf = g_coef[e];
    int slot = atomicAdd(&g_cursor[d], 1);
    g_ecsr[slot] = make_float4(cf.x, cf.y, __int_as_float(s), 0.f);
}

// ============================================================
// Kernel 2: edge MLP via tensor cores (3xTF32), fused epilogue
// 128 edges/block [round-15 proven config]; We via pre-split cp.async
// ============================================================
#define EA_STR 68
#define EB_STR 40
#define EOFF_AL 8704            // 128*68
#define EOFF_BH 17408
#define EOFF_BL 19968           // +64*40
#define EOFF_W2 22528
#define EOFF_SB 22592
#define ESMEM_BYTES ((22592 + 40) * 4)   // 90528 B

__global__ __launch_bounds__(256, 2)
void edge_mlp_tc(const float* __restrict__ edge_emb,  // [E,64]
                 const float* __restrict__ br1,       // [32]
                 const float* __restrict__ Wr2,       // [32,2]
                 const float* __restrict__ br2,       // [2]
                 const int*   __restrict__ eidx,      // [2,E]
                 int E)
{
    extern __shared__ unsigned sm_u[];
    unsigned* AsH = sm_u;
    unsigned* AsL = sm_u + EOFF_AL;
    unsigned* BsH = sm_u + EOFF_BH;
    unsigned* BsL = sm_u + EOFF_BL;
    float* sWr2   = reinterpret_cast<float*>(sm_u + EOFF_W2);
    float* sb     = reinterpret_cast<float*>(sm_u + EOFF_SB);
    float* Hs     = reinterpret_cast<float*>(sm_u);   // [128][36], reused after mainloop

    const int tid  = threadIdx.x;
    const int lane = tid & 31;
    const int warp = tid >> 5;
    const int gid  = lane >> 2;
    const int tg   = lane & 3;
    const int eb   = blockIdx.x * 128;

    // stage We (pre-split) via cp.async: 2 float4 per thread x hi/lo
#pragma unroll
    for (int j = 0; j < 2; j++) {
        int idx = tid + 256 * j;
        int k = idx >> 3, c4 = idx & 7;
        cp_async16(&BsH[k * EB_STR + c4 * 4], g_eWH + k * 32 + c4 * 4);
        cp_async16(&BsL[k * EB_STR + c4 * 4], g_eWL + k * 32 + c4 * 4);
    }
    CP_COMMIT();

    if (tid < 64) sWr2[tid] = Wr2[tid];
    if (tid < 32) sb[tid] = br1[tid];
    if (tid < 2)  sb[32 + tid] = br2[tid];

    // stage A (128 edge rows x 64), LDG + split (overlaps We cp.async)
#pragma unroll
    for (int j = 0; j < 8; j++) {
        int idx = tid + 256 * j;
        int e = idx >> 4, q = idx & 15;
        float4 v = *reinterpret_cast<const float4*>(edge_emb + (size_t)(eb + e) * 64 + q * 4);
        unsigned* dh = &AsH[e * EA_STR + q * 4];
        unsigned* dl = &AsL[e * EA_STR + q * 4];
        split_tf32(v.x, dh[0], dl[0]);
        split_tf32(v.y, dh[1], dl[1]);
        split_tf32(v.z, dh[2], dl[2]);
        split_tf32(v.w, dh[3], dl[3]);
    }
    CP_WAIT0();
    __syncthreads();

    float4 acc[4];
#pragma unroll
    for (int nf = 0; nf < 4; nf++) acc[nf] = make_float4(0.f, 0.f, 0.f, 0.f);

    const int row0 = warp * 16 + gid;
#pragma unroll
    for (int k8 = 0; k8 < 8; k8++) {
        const int kc = k8 * 8 + tg;
        unsigned aH0 = AsH[row0 * EA_STR + kc];
        unsigned aH1 = AsH[(row0 + 8) * EA_STR + kc];
        unsigned aH2 = AsH[row0 * EA_STR + kc + 4];
        unsigned aH3 = AsH[(row0 + 8) * EA_STR + kc + 4];
        unsigned aL0 = AsL[row0 * EA_STR + kc];
        unsigned aL1 = AsL[(row0 + 8) * EA_STR + kc];
        unsigned aL2 = AsL[row0 * EA_STR + kc + 4];
        unsigned aL3 = AsL[(row0 + 8) * EA_STR + kc + 4];
#pragma unroll
        for (int nf = 0; nf < 4; nf++) {
            int n = nf * 8 + gid;
            unsigned bH0 = BsH[kc * EB_STR + n];
            unsigned bH1 = BsH[(kc + 4) * EB_STR + n];
            unsigned bL0 = BsL[kc * EB_STR + n];
            unsigned bL1 = BsL[(kc + 4) * EB_STR + n];
            mma_tf32(acc[nf], aH0, aH1, aH2, aH3, bL0, bL1);
            mma_tf32(acc[nf], aL0, aL1, aL2, aL3, bH0, bH1);
            mma_tf32(acc[nf], aH0, aH1, aH2, aH3, bH0, bH1);
        }
    }
    __syncthreads();

#pragma unroll
    for (int nf = 0; nf < 4; nf++) {
        int n0 = nf * 8 + 2 * tg;
        *reinterpret_cast<float2*>(&Hs[row0 * 36 + n0])       = make_float2(acc[nf].x, acc[nf].y);
        *reinterpret_cast<float2*>(&Hs[(row0 + 8) * 36 + n0]) = make_float2(acc[nf].z, acc[nf].w);
    }
    __syncthreads();

    const int eg = tid >> 2;
    const int dg = tid & 3;
#pragma unroll
    for (int i = 0; i < 2; i++) {
        int le = eg + 64 * i;
        int ge = eb + le;
        int s = eidx[ge];
        int d = eidx[E + ge];
        float4 a0  = *reinterpret_cast<const float4*>(&Hs[le * 36 + dg * 8]);
        float4 a1  = *reinterpret_cast<const float4*>(&Hs[le * 36 + dg * 8 + 4]);
        float4 hs0 = *reinterpret_cast<const float4*>(g_hs + s * 32 + dg * 8);
        float4 hs1 = *reinterpret_cast<const float4*>(g_hs + s * 32 + dg * 8 + 4);
        float4 hd0 = *reinterpret_cast<const float4*>(g_hd + d * 32 + dg * 8);
        float4 hd1 = *reinterpret_cast<const float4*>(g_hd + d * 32 + dg * 8 + 4);
        float av[8]  = {a0.x, a0.y, a0.z, a0.w, a1.x, a1.y, a1.z, a1.w};
        float add[8] = {hs0.x + hd0.x, hs0.y + hd0.y, hs0.z + hd0.z, hs0.w + hd0.w,
                        hs1.x + hd1.x, hs1.y + hd1.y, hs1.z + hd1.z, hs1.w + hd1.w};
        float v0 = 0.f, v1 = 0.f;
#pragma unroll
        for (int j = 0; j < 8; j++) {
            float h = av[j] + add[j] + sb[dg * 8 + j];
            h = (h >= 0.f) ? h : 0.01f * h;
            v0 = fmaf(h, sWr2[(dg * 8 + j) * 2 + 0], v0);
            v1 = fmaf(h, sWr2[(dg * 8 + j) * 2 + 1], v1);
        }
        v0 += __shfl_xor_sync(0xffffffffu, v0, 1);
        v0 += __shfl_xor_sync(0xffffffffu, v0, 2);
        v1 += __shfl_xor_sync(0xffffffffu, v1, 1);
        v1 += __shfl_xor_sync(0xffffffffu, v1, 2);
        if (dg == 0) {
            float x = v0 + sb[32] + 1.0f;
            float elen = fmaxf(x, 0.f) + log1pf(expf(-fabsf(x)));
            float y = v1 + sb[33] - 2.0f;
            float sg = 1.0f / (1.0f + expf(-y));
            g_coef[ge] = make_float2(elen, 2.0f * sg);
        }
    }
}

// ============================================================
// Refiner: quad-per-node gather (round-13 proven)
// ============================================================
__global__ __launch_bounds__(256)
void refine_step_kernel(const float4* __restrict__ cin, float4* __restrict__ cout,
                        float* __restrict__ out_coords, int last, int N)
{
    const int tid = threadIdx.x;
    const int q   = tid & 3;
    const int nl  = tid >> 2;
    const int n   = blockIdx.x * 64 + nl;
    if (n >= N) return;

    float4 c = cin[n];
    const int p = g_ptr[n];
    const int d = g_deg[n];

    float ax = 0.f, ay = 0.f, az = 0.f;
    for (int i = q; i < d; i += 4) {
        float4 er = g_ecsr[p + i];
        int s = __float_as_int(er.z);
        float4 cs = __ldg(cin + s);
        float dx = c.x - cs.x, dy = c.y - cs.y, dz = c.z - cs.z;
        float dist = sqrtf(dx * dx + dy * dy + dz * dz);
        float f = __fdividef(er.y * (er.x - dist), dist + EPSV);
        ax = fmaf(f, dx, ax);
        ay = fmaf(f, dy, ay);
        az = fmaf(f, dz, az);
    }
    ax += __shfl_xor_sync(0xffffffffu, ax, 1);
    ax += __shfl_xor_sync(0xffffffffu, ax, 2);
    ay += __shfl_xor_sync(0xffffffffu, ay, 1);
    ay += __shfl_xor_sync(0xffffffffu, ay, 2);
    az += __shfl_xor_sync(0xffffffffu, az, 1);
    az += __shfl_xor_sync(0xffffffffu, az, 2);

    if (q == 0) {
        float an = sqrtf(ax * ax + ay * ay + az * az) + EPSV;
        float sc = fminf(an, 0.5f) / an;
        c.x += ax * sc; c.y += ay * sc; c.z += az * sc;
        cout[n] = c;
        if (last) {
            out_coords[n * 3 + 0] = c.x;
            out_coords[n * 3 + 1] = c.y;
            out_coords[n * 3 + 2] = c.z;
        }
    }
}

// ============================================================
// launch — two-stream fork/join (graph-capturable)
// ============================================================
extern "C" void kernel_launch(void* const* d_in, const int* in_sizes, int n_in,
                              void* d_out, int out_size)
{
    const float* node_emb  = (const float*)d_in[0];
    const float* edge_emb  = (const float*)d_in[1];
    const float* cart_init = (const float*)d_in[2];
    const float* Wt1       = (const float*)d_in[3];
    const float* bt1       = (const float*)d_in[4];
    const float* Wt2       = (const float*)d_in[5];
    const float* bt2       = (const float*)d_in[6];
    const float* Wr1       = (const float*)d_in[7];
    const float* br1       = (const float*)d_in[8];
    const float* Wr2       = (const float*)d_in[9];
    const float* br2       = (const float*)d_in[10];
    const int*   eidx      = (const int*)d_in[11];

    const int M = in_sizes[0] / NH;        // 50000
    const int E = in_sizes[1] / EH;        // 800000

    float* out = (float*)d_out;
    float* out_coords  = out;
    float* out_torsion = out + (size_t)M * 3;

    static cudaStream_t s2 = nullptr;
    static cudaEvent_t evFork = nullptr, evJoin = nullptr;
    if (!s2) {
        cudaStreamCreateWithFlags(&s2, cudaStreamNonBlocking);
        cudaEventCreateWithFlags(&evFork, cudaEventDisableTiming);
        cudaEventCreateWithFlags(&evJoin, cudaEventDisableTiming);
        cudaFuncSetAttribute(edge_mlp_tc, cudaFuncAttributeMaxDynamicSharedMemorySize,
                             ESMEM_BYTES);
        cudaFuncSetAttribute(node_gemm_tc, cudaFuncAttributeMaxDynamicSharedMemorySize,
                             NG_SMEM_BYTES);
    }

    const int nb_nodes = (M + 255) / 256;
    const int nb_edges = (E + 255) / 256;
    const int nb_emlp  = (E + 127) / 128;
    const int nb_ref   = (M + 63) / 64;
    const int nb_split = (256 * 192 + 64 * 32 + 255) / 256;

    // fork: CSR-build chain on side stream s2
    cudaEventRecord(evFork, 0);
    cudaStreamWaitEvent(s2, evFork, 0);

    // --- call order: capture index 3 = node_gemm_tc (profiled) ---
    presplit_kernel<<<nb_split, 256>>>(Wt1, Wr1);                                // 0
    init_kernel<<<nb_nodes, 256, 0, s2>>>(cart_init, M);                         // 1
    count_kernel<<<nb_edges, 256, 0, s2>>>(eidx, E);                             // 2
    node_gemm_tc<<<(M + TBM - 1) / TBM, 256, NG_SMEM_BYTES>>>(node_emb, bt1,     // 3
                                               Wt2, bt2, out_torsion, M);
    edge_mlp_tc<<<nb_emlp, 256, ESMEM_BYTES>>>(edge_emb, br1, Wr2, br2,          // 4
                                               eidx, E);
    scan1_kernel<<<nb_nodes, 256, 0, s2>>>(M);                                   // 5
    scan2_kernel<<<1, 256, 0, s2>>>(nb_nodes);                                   // 6
    scan3_kernel<<<nb_nodes, 256, 0, s2>>>(M);                                   // 7

    // join: fill needs cursor (s2) + coef (stream 0)
    cudaEventRecord(evJoin, s2);
    cudaStreamWaitEvent(0, evJoin, 0);

    fill_kernel<<<nb_edges, 256>>>(eidx, E);                                     // 8

    float4* bufs[2];
    cudaGetSymbolAddress((void**)&bufs[0], g_cA);
    cudaGetSymbolAddress((void**)&bufs[1], g_cB);
    for (int s = 0; s < NSTEPS; s++) {
        refine_step_kernel<<<nb_ref, 256>>>(bufs[s & 1], bufs[(s + 1) & 1],
                                            out_coords, (s == NSTEPS - 1) ? 1 : 0, M);
    }
}